// round 5
// baseline (speedup 1.0000x reference)
#include <cuda_runtime.h>
#include <cuda_bf16.h>
#include <stdint.h>

#define N_NODES 100000
#define NE      1600000
#define IN_DIM  256
#define HID     128
#define SCAN_B  ((N_NODES + 1023) / 1024)   // 98 scan blocks

// ---------------- scratch (static device globals; no allocation) ------------
__device__ int   d_src32[NE];
__device__ int   d_dst32[NE];
__device__ int   d_srcs[NE];       // CSR-permuted source indices (by dst)
__device__ int   d_cnt[N_NODES];
__device__ int   d_rowptr[N_NODES];
__device__ int   d_cursor[N_NODES];
__device__ float d_dinv[N_NODES];
__device__ int   d_bsum[SCAN_B];
__device__ int   d_boff[SCAN_B];
__device__ float d_h[(size_t)N_NODES * HID];
__device__ float d_t[(size_t)N_NODES * HID];
__device__ int   g_is64;

// packed f32x2 fma: d.lo += a.lo*b.lo ; d.hi += a.hi*b.hi  (SASS FFMA2)
__device__ __forceinline__ void fma2(unsigned long long& d,
                                     unsigned long long a,
                                     unsigned long long b) {
    asm("fma.rn.f32x2 %0, %1, %2, %0;" : "+l"(d) : "l"(a), "l"(b));
}
__device__ __forceinline__ float lo_plus_hi(unsigned long long v) {
    float x, y;
    asm("mov.b64 {%0, %1}, %2;" : "=f"(x), "=f"(y) : "l"(v));
    return x + y;
}

// ---------------- edge dtype detection + conversion + count ------------------
__global__ void k_detect(const int* __restrict__ w) {
    int ok = 1;
    for (int i = 0; i < 64; i++) {
        if (w[2 * i + 1] != 0) { ok = 0; break; }
    }
    g_is64 = ok;
}

__global__ void k_zero_cnt() {
    int i = blockIdx.x * blockDim.x + threadIdx.x;
    if (i < N_NODES) d_cnt[i] = 0;
}

__global__ void k_convert_count(const void* __restrict__ ei) {
    int e = blockIdx.x * blockDim.x + threadIdx.x;
    if (e >= NE) return;
    int s, d;
    if (g_is64) {
        const long long* p = (const long long*)ei;
        s = (int)p[e];
        d = (int)p[e + NE];
    } else {
        const int* p = (const int*)ei;
        s = p[e];
        d = p[e + NE];
    }
    d_src32[e] = s;
    d_dst32[e] = d;
    atomicAdd(&d_cnt[d], 1);
}

// ---------------- parallel 3-phase scan --------------------------------------
__global__ void __launch_bounds__(1024) k_scan1() {
    __shared__ int wsum[32];
    const int tid  = threadIdx.x;
    const int lane = tid & 31;
    const int w    = tid >> 5;
    const int gid  = blockIdx.x * 1024 + tid;

    int c = (gid < N_NODES) ? d_cnt[gid] : 0;
    int v = c;
#pragma unroll
    for (int o = 1; o < 32; o <<= 1) {
        int t = __shfl_up_sync(0xFFFFFFFFu, v, o);
        if (lane >= o) v += t;
    }
    if (lane == 31) wsum[w] = v;
    __syncthreads();
    if (w == 0) {
        int s = wsum[lane];
#pragma unroll
        for (int o = 1; o < 32; o <<= 1) {
            int t = __shfl_up_sync(0xFFFFFFFFu, s, o);
            if (lane >= o) s += t;
        }
        wsum[lane] = s;
    }
    __syncthreads();
    int excl = v - c + (w ? wsum[w - 1] : 0);
    if (gid < N_NODES) d_rowptr[gid] = excl;
    if (tid == 1023) d_bsum[blockIdx.x] = wsum[31];
}

__global__ void k_scan2() {
    __shared__ int s[128];
    const int t = threadIdx.x;
    s[t] = (t < SCAN_B) ? d_bsum[t] : 0;
    __syncthreads();
    for (int o = 1; o < 128; o <<= 1) {
        int v = (t >= o) ? s[t - o] : 0;
        __syncthreads();
        s[t] += v;
        __syncthreads();
    }
    if (t < SCAN_B) d_boff[t] = (t ? s[t - 1] : 0);
}

__global__ void k_scan3() {
    const int gid = blockIdx.x * blockDim.x + threadIdx.x;
    if (gid >= N_NODES) return;
    int rp = d_rowptr[gid] + d_boff[gid >> 10];
    d_rowptr[gid] = rp;
    d_cursor[gid] = rp;
    d_dinv[gid] = rsqrtf((float)(d_cnt[gid] + 1));  // +1 = self loop
}

__global__ void k_fill() {
    int e = blockIdx.x * blockDim.x + threadIdx.x;
    if (e >= NE) return;
    int dd = d_dst32[e];
    int pos = atomicAdd(&d_cursor[dd], 1);
    d_srcs[pos] = d_src32[e];
}

// ---------------- GEMM: C[M,128] = act(A[M,K] @ W[K,128] + b) ---------------
// 256 threads/block; block computes 64 rows x 128 cols.
// warp w -> rows [w*8,+8), lane -> cols [lane*4,+4).
// FFMA2 with K-packing: acc.lo sums even-k, acc.hi odd-k products.
template <int K, bool RELU, bool BIAS>
__global__ void __launch_bounds__(256) k_gemm(const float* __restrict__ A,
                                              const float* __restrict__ W,
                                              const float* __restrict__ bias,
                                              float* __restrict__ C, int M) {
    __shared__ float  sA[64][32];       // [row][k]        8 KB
    __shared__ float2 sW2[16][128];     // [k/2][col]={w_even,w_odd}  16 KB

    const int tid  = threadIdx.x;
    const int warp = tid >> 5;
    const int lane = tid & 31;
    const int row0 = blockIdx.x * 64;

    unsigned long long acc[8][4];
#pragma unroll
    for (int r = 0; r < 8; r++)
#pragma unroll
        for (int c = 0; c < 4; c++) acc[r][c] = 0ull;

    for (int kc = 0; kc < K; kc += 32) {
        // A tile: 64 rows x 32 k (512 float4)
#pragma unroll
        for (int i = 0; i < 2; i++) {
            int idx = tid + i * 256;
            int r = idx >> 3, c = idx & 7;
            int grow = row0 + r;
            float4 v = make_float4(0.f, 0.f, 0.f, 0.f);
            if (grow < M)
                v = *(const float4*)(A + (size_t)grow * K + kc + c * 4);
            *(float4*)(&sA[r][c * 4]) = v;
        }
        // W tile, k-interleaved: sW2[kk2][c] = {W[kc+2kk2][c], W[kc+2kk2+1][c]}
#pragma unroll
        for (int i = 0; i < 8; i++) {
            int idx = tid + i * 256;        // 0..2047
            int kk2 = idx >> 7, c = idx & 127;
            float2 p;
            p.x = W[(size_t)(kc + 2 * kk2)     * 128 + c];
            p.y = W[(size_t)(kc + 2 * kk2 + 1) * 128 + c];
            sW2[kk2][c] = p;
        }
        __syncthreads();
#pragma unroll
        for (int kk2 = 0; kk2 < 16; kk2++) {
            ulonglong2 w01 = *(const ulonglong2*)(&sW2[kk2][lane * 4]);
            ulonglong2 w23 = *(const ulonglong2*)(&sW2[kk2][lane * 4 + 2]);
#pragma unroll
            for (int r = 0; r < 8; r++) {
                unsigned long long ap =
                    *(const unsigned long long*)(&sA[warp * 8 + r][kk2 * 2]);
                fma2(acc[r][0], ap, w01.x);
                fma2(acc[r][1], ap, w01.y);
                fma2(acc[r][2], ap, w23.x);
                fma2(acc[r][3], ap, w23.y);
            }
        }
        __syncthreads();
    }

    float4 bv = make_float4(0.f, 0.f, 0.f, 0.f);
    if (BIAS) bv = *(const float4*)(bias + lane * 4);
#pragma unroll
    for (int r = 0; r < 8; r++) {
        int grow = row0 + warp * 8 + r;
        if (grow < M) {
            float4 o;
            o.x = lo_plus_hi(acc[r][0]) + bv.x;
            o.y = lo_plus_hi(acc[r][1]) + bv.y;
            o.z = lo_plus_hi(acc[r][2]) + bv.z;
            o.w = lo_plus_hi(acc[r][3]) + bv.w;
            if (RELU) {
                o.x = fmaxf(o.x, 0.f); o.y = fmaxf(o.y, 0.f);
                o.z = fmaxf(o.z, 0.f); o.w = fmaxf(o.w, 0.f);
            }
            *(float4*)(C + (size_t)grow * 128 + lane * 4) = o;
        }
    }
}

// ---------------- GCN aggregate: warp per destination node ------------------
__global__ void __launch_bounds__(256) k_aggregate(const float* __restrict__ t,
                                                   const float* __restrict__ b,
                                                   float* __restrict__ hout) {
    const int wid  = (blockIdx.x * blockDim.x + threadIdx.x) >> 5;
    const int lane = threadIdx.x & 31;
    if (wid >= N_NODES) return;
    const int d = wid;

    const float4* t4 = (const float4*)t;
    const float dd = d_dinv[d];

    float4 a0 = t4[d * 32 + lane];   // self term
    a0.x *= dd; a0.y *= dd; a0.z *= dd; a0.w *= dd;
    float4 a1 = make_float4(0.f, 0.f, 0.f, 0.f);

    const int beg = d_rowptr[d];
    const int num = d_cnt[d];
    int j = 0;
    for (; j + 2 <= num; j += 2) {
        int s0 = d_srcs[beg + j];
        int s1 = d_srcs[beg + j + 1];
        float ds0 = d_dinv[s0];
        float ds1 = d_dinv[s1];
        float4 v0 = t4[s0 * 32 + lane];
        float4 v1 = t4[s1 * 32 + lane];
        a0.x += v0.x * ds0; a0.y += v0.y * ds0;
        a0.z += v0.z * ds0; a0.w += v0.w * ds0;
        a1.x += v1.x * ds1; a1.y += v1.y * ds1;
        a1.z += v1.z * ds1; a1.w += v1.w * ds1;
    }
    if (j < num) {
        int s = d_srcs[beg + j];
        float ds = d_dinv[s];
        float4 v = t4[s * 32 + lane];
        a0.x += v.x * ds; a0.y += v.y * ds;
        a0.z += v.z * ds; a0.w += v.w * ds;
    }

    float4 bv = ((const float4*)b)[lane];
    float4 o;
    o.x = (a0.x + a1.x) * dd + bv.x;
    o.y = (a0.y + a1.y) * dd + bv.y;
    o.z = (a0.z + a1.z) * dd + bv.z;
    o.w = (a0.w + a1.w) * dd + bv.w;
    ((float4*)hout)[(size_t)d * 32 + lane] = o;
}

// ---------------- head: out[N,2] = h @ Wh + bh ------------------------------
__global__ void __launch_bounds__(256) k_head(const float* __restrict__ h,
                                              const float* __restrict__ Wh,
                                              const float* __restrict__ bh,
                                              float* __restrict__ out) {
    const int wid  = (blockIdx.x * blockDim.x + threadIdx.x) >> 5;
    const int lane = threadIdx.x & 31;
    if (wid >= N_NODES) return;

    float4 v = ((const float4*)(h + (size_t)wid * 128))[lane];
    float4 w0 = *(const float4*)(Wh + lane * 8);
    float4 w1 = *(const float4*)(Wh + lane * 8 + 4);
    float p0 = v.x * w0.x + v.y * w0.z + v.z * w1.x + v.w * w1.z;
    float p1 = v.x * w0.y + v.y * w0.w + v.z * w1.y + v.w * w1.w;
#pragma unroll
    for (int off = 16; off; off >>= 1) {
        p0 += __shfl_xor_sync(0xFFFFFFFFu, p0, off);
        p1 += __shfl_xor_sync(0xFFFFFFFFu, p1, off);
    }
    if (lane == 0) {
        out[wid * 2 + 0] = p0 + bh[0];
        out[wid * 2 + 1] = p1 + bh[1];
    }
}

// ---------------- launch -----------------------------------------------------
extern "C" void kernel_launch(void* const* d_in, const int* in_sizes, int n_in,
                              void* d_out, int out_size) {
    const void*  ei = d_in[0];
    const float* x  = (const float*)d_in[1];
    const float* Wi = (const float*)d_in[2];
    const float* bi = (const float*)d_in[3];
    const float* W1 = (const float*)d_in[4];
    const float* b1 = (const float*)d_in[5];
    const float* W2 = (const float*)d_in[6];
    const float* b2 = (const float*)d_in[7];
    const float* Wh = (const float*)d_in[8];
    const float* bh = (const float*)d_in[9];
    float* out = (float*)d_out;

    float *h, *t;
    cudaGetSymbolAddress((void**)&h, d_h);
    cudaGetSymbolAddress((void**)&t, d_t);

    const int EB = (NE + 255) / 256;
    const int NB = (N_NODES + 255) / 256;
    const int GB = (N_NODES + 63) / 64;
    const int WB = (N_NODES + 7) / 8;

    // 1. edge dtype + CSR by destination + degree normalization
    k_detect<<<1, 1>>>((const int*)ei);
    k_zero_cnt<<<NB, 256>>>();
    k_convert_count<<<EB, 256>>>(ei);
    k_scan1<<<SCAN_B, 1024>>>();
    k_scan2<<<1, 128>>>();
    k_scan3<<<NB, 256>>>();
    k_fill<<<EB, 256>>>();

    // 2. node init: h = relu(x @ Wi + bi)
    k_gemm<IN_DIM, true, true><<<GB, 256>>>(x, Wi, bi, h, N_NODES);

    // 3. GCN layer 1
    k_gemm<HID, false, false><<<GB, 256>>>(h, W1, nullptr, t, N_NODES);
    k_aggregate<<<WB, 256>>>(t, b1, h);

    // 4. GCN layer 2
    k_gemm<HID, false, false><<<GB, 256>>>(h, W2, nullptr, t, N_NODES);
    k_aggregate<<<WB, 256>>>(t, b2, h);

    // 5. head
    k_head<<<WB, 256>>>(h, Wh, bh, out);
}

// round 6
// speedup vs baseline: 1.7601x; 1.7601x over previous
#include <cuda_runtime.h>
#include <cuda_bf16.h>
#include <stdint.h>

#define N_NODES 100000
#define NE      1600000
#define IN_DIM  256
#define HID     128
#define SCAN_B  ((N_NODES + 1023) / 1024)   // 98 scan blocks

// ---------------- scratch (static device globals; no allocation) ------------
__device__ int   d_src32[NE];
__device__ int   d_dst32[NE];
__device__ int   d_srcs[NE];       // CSR-permuted source indices (by dst)
__device__ int   d_cnt[N_NODES];
__device__ int   d_rowptr[N_NODES];
__device__ int   d_cursor[N_NODES];
__device__ float d_dinv[N_NODES];
__device__ int   d_bsum[SCAN_B];
__device__ int   d_boff[SCAN_B];
__device__ float d_h[(size_t)N_NODES * HID];
__device__ float d_t[(size_t)N_NODES * HID];
__device__ int   g_is64;

// ---------------- helpers -----------------------------------------------------
// pack two floats into bf16x2: low half = first arg (even k), high = second.
__device__ __forceinline__ unsigned pack_bf16x2(float k_even, float k_odd) {
    unsigned r;
    asm("cvt.rn.bf16x2.f32 %0, %1, %2;" : "=r"(r) : "f"(k_odd), "f"(k_even));
    return r;
}
__device__ __forceinline__ void mma_bf16(float* c, unsigned a0, unsigned a1,
                                         unsigned a2, unsigned a3,
                                         unsigned b0, unsigned b1) {
    asm("mma.sync.aligned.m16n8k16.row.col.f32.bf16.bf16.f32 "
        "{%0,%1,%2,%3}, {%4,%5,%6,%7}, {%8,%9}, {%0,%1,%2,%3};"
        : "+f"(c[0]), "+f"(c[1]), "+f"(c[2]), "+f"(c[3])
        : "r"(a0), "r"(a1), "r"(a2), "r"(a3), "r"(b0), "r"(b1));
}

// ---------------- edge dtype detection + conversion + count ------------------
__global__ void k_detect(const int* __restrict__ w) {
    int ok = 1;
    for (int i = 0; i < 64; i++) {
        if (w[2 * i + 1] != 0) { ok = 0; break; }
    }
    g_is64 = ok;
}

__global__ void k_zero_cnt() {
    int i = blockIdx.x * blockDim.x + threadIdx.x;
    if (i < N_NODES) d_cnt[i] = 0;
}

__global__ void k_convert_count(const void* __restrict__ ei) {
    int e = blockIdx.x * blockDim.x + threadIdx.x;
    if (e >= NE) return;
    int s, d;
    if (g_is64) {
        const long long* p = (const long long*)ei;
        s = (int)p[e];
        d = (int)p[e + NE];
    } else {
        const int* p = (const int*)ei;
        s = p[e];
        d = p[e + NE];
    }
    d_src32[e] = s;
    d_dst32[e] = d;
    atomicAdd(&d_cnt[d], 1);
}

// ---------------- parallel 3-phase scan --------------------------------------
__global__ void __launch_bounds__(1024) k_scan1() {
    __shared__ int wsum[32];
    const int tid  = threadIdx.x;
    const int lane = tid & 31;
    const int w    = tid >> 5;
    const int gid  = blockIdx.x * 1024 + tid;

    int c = (gid < N_NODES) ? d_cnt[gid] : 0;
    int v = c;
#pragma unroll
    for (int o = 1; o < 32; o <<= 1) {
        int t = __shfl_up_sync(0xFFFFFFFFu, v, o);
        if (lane >= o) v += t;
    }
    if (lane == 31) wsum[w] = v;
    __syncthreads();
    if (w == 0) {
        int s = wsum[lane];
#pragma unroll
        for (int o = 1; o < 32; o <<= 1) {
            int t = __shfl_up_sync(0xFFFFFFFFu, s, o);
            if (lane >= o) s += t;
        }
        wsum[lane] = s;
    }
    __syncthreads();
    int excl = v - c + (w ? wsum[w - 1] : 0);
    if (gid < N_NODES) d_rowptr[gid] = excl;
    if (tid == 1023) d_bsum[blockIdx.x] = wsum[31];
}

__global__ void k_scan2() {
    __shared__ int s[128];
    const int t = threadIdx.x;
    s[t] = (t < SCAN_B) ? d_bsum[t] : 0;
    __syncthreads();
    for (int o = 1; o < 128; o <<= 1) {
        int v = (t >= o) ? s[t - o] : 0;
        __syncthreads();
        s[t] += v;
        __syncthreads();
    }
    if (t < SCAN_B) d_boff[t] = (t ? s[t - 1] : 0);
}

__global__ void k_scan3() {
    const int gid = blockIdx.x * blockDim.x + threadIdx.x;
    if (gid >= N_NODES) return;
    int rp = d_rowptr[gid] + d_boff[gid >> 10];
    d_rowptr[gid] = rp;
    d_cursor[gid] = rp;
    d_dinv[gid] = rsqrtf((float)(d_cnt[gid] + 1));  // +1 = self loop
}

__global__ void k_fill() {
    int e = blockIdx.x * blockDim.x + threadIdx.x;
    if (e >= NE) return;
    int dd = d_dst32[e];
    int pos = atomicAdd(&d_cursor[dd], 1);
    d_srcs[pos] = d_src32[e];
}

// ---------------- tensor-core GEMM ------------------------------------------
// C[M,128] = act(A[M,K] @ W[K,128] + b), split-bf16 3-term compensation.
// Block: 256 threads / 8 warps, tile 128 rows x 128 cols, BK=32.
// smem: packed bf16x2 k-pairs, [row][pair] stride 20 (bank-conflict-free).
#define PAD 20
template <int K, bool RELU, bool BIAS>
__global__ void __launch_bounds__(256) k_gemm_tc(const float* __restrict__ A,
                                                 const float* __restrict__ W,
                                                 const float* __restrict__ bias,
                                                 float* __restrict__ C, int M) {
    __shared__ unsigned sAhi[128][PAD];   // [row][kp]  (16 used + 4 pad)
    __shared__ unsigned sAlo[128][PAD];
    __shared__ unsigned sWhi[128][PAD];   // [n][kp]  (transposed)
    __shared__ unsigned sWlo[128][PAD];

    const int tid   = threadIdx.x;
    const int warp  = tid >> 5;
    const int lane  = tid & 31;
    const int g     = lane >> 2;          // group id (0..7)
    const int tig   = lane & 3;           // thread in group
    const int mbase = warp * 16;          // warp's row stripe in tile
    const int row0  = blockIdx.x * 128;

    float acc[16][4];
#pragma unroll
    for (int nb = 0; nb < 16; nb++)
#pragma unroll
        for (int i = 0; i < 4; i++) acc[nb][i] = 0.f;

    for (int kc = 0; kc < K; kc += 32) {
        // ---- A tile: 128 rows x 32 k = 1024 float4 --------------------------
#pragma unroll
        for (int i = 0; i < 4; i++) {
            int idx = tid + i * 256;          // 0..1023
            int r = idx >> 3, c4 = idx & 7;   // c4: float4 index (k = c4*4..+3)
            int grow = row0 + r;
            float4 v = make_float4(0.f, 0.f, 0.f, 0.f);
            if (grow < M)
                v = *(const float4*)(A + (size_t)grow * K + kc + c4 * 4);
            float hx = __bfloat162float(__float2bfloat16(v.x));
            float hy = __bfloat162float(__float2bfloat16(v.y));
            float hz = __bfloat162float(__float2bfloat16(v.z));
            float hw = __bfloat162float(__float2bfloat16(v.w));
            sAhi[r][c4 * 2 + 0] = pack_bf16x2(hx, hy);
            sAhi[r][c4 * 2 + 1] = pack_bf16x2(hz, hw);
            sAlo[r][c4 * 2 + 0] = pack_bf16x2(v.x - hx, v.y - hy);
            sAlo[r][c4 * 2 + 1] = pack_bf16x2(v.z - hz, v.w - hw);
        }
        // ---- W tile (transposed): sW[n][kp] = {W[kc+2kp][n], W[kc+2kp+1][n]}
#pragma unroll
        for (int i = 0; i < 8; i++) {
            int idx = tid + i * 256;          // 0..2047
            int n = idx & 127, kp = idx >> 7; // kp 0..15
            float w0 = W[(size_t)(kc + 2 * kp)     * 128 + n];
            float w1 = W[(size_t)(kc + 2 * kp + 1) * 128 + n];
            float h0 = __bfloat162float(__float2bfloat16(w0));
            float h1 = __bfloat162float(__float2bfloat16(w1));
            sWhi[n][kp] = pack_bf16x2(h0, h1);
            sWlo[n][kp] = pack_bf16x2(w0 - h0, w1 - h1);
        }
        __syncthreads();

        // ---- MMAs: two k16 sub-chunks ---------------------------------------
#pragma unroll
        for (int kk = 0; kk < 2; kk++) {
            const int kp = kk * 8 + tig;
            unsigned ah0 = sAhi[mbase + g][kp];
            unsigned ah1 = sAhi[mbase + g + 8][kp];
            unsigned ah2 = sAhi[mbase + g][kp + 4];
            unsigned ah3 = sAhi[mbase + g + 8][kp + 4];
            unsigned al0 = sAlo[mbase + g][kp];
            unsigned al1 = sAlo[mbase + g + 8][kp];
            unsigned al2 = sAlo[mbase + g][kp + 4];
            unsigned al3 = sAlo[mbase + g + 8][kp + 4];
#pragma unroll
            for (int nb = 0; nb < 16; nb++) {
                unsigned bh0 = sWhi[nb * 8 + g][kp];
                unsigned bh1 = sWhi[nb * 8 + g][kp + 4];
                unsigned bl0 = sWlo[nb * 8 + g][kp];
                unsigned bl1 = sWlo[nb * 8 + g][kp + 4];
                mma_bf16(acc[nb], ah0, ah1, ah2, ah3, bh0, bh1);  // hi*hi
                mma_bf16(acc[nb], ah0, ah1, ah2, ah3, bl0, bl1);  // hi*lo
                mma_bf16(acc[nb], al0, al1, al2, al3, bh0, bh1);  // lo*hi
            }
        }
        __syncthreads();
    }

    // ---- epilogue -----------------------------------------------------------
    const int r0 = row0 + mbase + g;
    const int r1 = r0 + 8;
#pragma unroll
    for (int nb = 0; nb < 16; nb++) {
        int col = nb * 8 + tig * 2;
        float b0 = 0.f, b1 = 0.f;
        if (BIAS) { b0 = bias[col]; b1 = bias[col + 1]; }
        float2 v0, v1;
        v0.x = acc[nb][0] + b0; v0.y = acc[nb][1] + b1;
        v1.x = acc[nb][2] + b0; v1.y = acc[nb][3] + b1;
        if (RELU) {
            v0.x = fmaxf(v0.x, 0.f); v0.y = fmaxf(v0.y, 0.f);
            v1.x = fmaxf(v1.x, 0.f); v1.y = fmaxf(v1.y, 0.f);
        }
        if (r0 < M) *(float2*)(C + (size_t)r0 * 128 + col) = v0;
        if (r1 < M) *(float2*)(C + (size_t)r1 * 128 + col) = v1;
    }
}

// ---------------- GCN aggregate: warp per destination node ------------------
__global__ void __launch_bounds__(256) k_aggregate(const float* __restrict__ t,
                                                   const float* __restrict__ b,
                                                   float* __restrict__ hout) {
    const int wid  = (blockIdx.x * blockDim.x + threadIdx.x) >> 5;
    const int lane = threadIdx.x & 31;
    if (wid >= N_NODES) return;
    const int d = wid;

    const float4* t4 = (const float4*)t;
    const float dd = d_dinv[d];

    float4 a0 = t4[d * 32 + lane];   // self term
    a0.x *= dd; a0.y *= dd; a0.z *= dd; a0.w *= dd;
    float4 a1 = make_float4(0.f, 0.f, 0.f, 0.f);

    const int beg = d_rowptr[d];
    const int num = d_cnt[d];
    int j = 0;
    for (; j + 2 <= num; j += 2) {
        int s0 = d_srcs[beg + j];
        int s1 = d_srcs[beg + j + 1];
        float ds0 = d_dinv[s0];
        float ds1 = d_dinv[s1];
        float4 v0 = t4[s0 * 32 + lane];
        float4 v1 = t4[s1 * 32 + lane];
        a0.x += v0.x * ds0; a0.y += v0.y * ds0;
        a0.z += v0.z * ds0; a0.w += v0.w * ds0;
        a1.x += v1.x * ds1; a1.y += v1.y * ds1;
        a1.z += v1.z * ds1; a1.w += v1.w * ds1;
    }
    if (j < num) {
        int s = d_srcs[beg + j];
        float ds = d_dinv[s];
        float4 v = t4[s * 32 + lane];
        a0.x += v.x * ds; a0.y += v.y * ds;
        a0.z += v.z * ds; a0.w += v.w * ds;
    }

    float4 bv = ((const float4*)b)[lane];
    float4 o;
    o.x = (a0.x + a1.x) * dd + bv.x;
    o.y = (a0.y + a1.y) * dd + bv.y;
    o.z = (a0.z + a1.z) * dd + bv.z;
    o.w = (a0.w + a1.w) * dd + bv.w;
    ((float4*)hout)[(size_t)d * 32 + lane] = o;
}

// ---------------- head: out[N,2] = h @ Wh + bh ------------------------------
__global__ void __launch_bounds__(256) k_head(const float* __restrict__ h,
                                              const float* __restrict__ Wh,
                                              const float* __restrict__ bh,
                                              float* __restrict__ out) {
    const int wid  = (blockIdx.x * blockDim.x + threadIdx.x) >> 5;
    const int lane = threadIdx.x & 31;
    if (wid >= N_NODES) return;

    float4 v = ((const float4*)(h + (size_t)wid * 128))[lane];
    float4 w0 = *(const float4*)(Wh + lane * 8);
    float4 w1 = *(const float4*)(Wh + lane * 8 + 4);
    float p0 = v.x * w0.x + v.y * w0.z + v.z * w1.x + v.w * w1.z;
    float p1 = v.x * w0.y + v.y * w0.w + v.z * w1.y + v.w * w1.w;
#pragma unroll
    for (int off = 16; off; off >>= 1) {
        p0 += __shfl_xor_sync(0xFFFFFFFFu, p0, off);
        p1 += __shfl_xor_sync(0xFFFFFFFFu, p1, off);
    }
    if (lane == 0) {
        out[wid * 2 + 0] = p0 + bh[0];
        out[wid * 2 + 1] = p1 + bh[1];
    }
}

// ---------------- launch -----------------------------------------------------
extern "C" void kernel_launch(void* const* d_in, const int* in_sizes, int n_in,
                              void* d_out, int out_size) {
    const void*  ei = d_in[0];
    const float* x  = (const float*)d_in[1];
    const float* Wi = (const float*)d_in[2];
    const float* bi = (const float*)d_in[3];
    const float* W1 = (const float*)d_in[4];
    const float* b1 = (const float*)d_in[5];
    const float* W2 = (const float*)d_in[6];
    const float* b2 = (const float*)d_in[7];
    const float* Wh = (const float*)d_in[8];
    const float* bh = (const float*)d_in[9];
    float* out = (float*)d_out;

    float *h, *t;
    cudaGetSymbolAddress((void**)&h, d_h);
    cudaGetSymbolAddress((void**)&t, d_t);

    const int EB = (NE + 255) / 256;
    const int NB = (N_NODES + 255) / 256;
    const int GB = (N_NODES + 127) / 128;     // tensor GEMM blocks (128 rows)
    const int WB = (N_NODES + 7) / 8;

    // 1. edge dtype + CSR by destination + degree normalization
    k_detect<<<1, 1>>>((const int*)ei);
    k_zero_cnt<<<NB, 256>>>();
    k_convert_count<<<EB, 256>>>(ei);
    k_scan1<<<SCAN_B, 1024>>>();
    k_scan2<<<1, 128>>>();
    k_scan3<<<NB, 256>>>();
    k_fill<<<EB, 256>>>();

    // 2. node init: h = relu(x @ Wi + bi)
    k_gemm_tc<IN_DIM, true, true><<<GB, 256>>>(x, Wi, bi, h, N_NODES);

    // 3. GCN layer 1
    k_gemm_tc<HID, false, false><<<GB, 256>>>(h, W1, nullptr, t, N_NODES);
    k_aggregate<<<WB, 256>>>(t, b1, h);

    // 4. GCN layer 2
    k_gemm_tc<HID, false, false><<<GB, 256>>>(h, W2, nullptr, t, N_NODES);
    k_aggregate<<<WB, 256>>>(t, b2, h);

    // 5. head
    k_head<<<WB, 256>>>(h, Wh, bh, out);
}